// round 16
// baseline (speedup 1.0000x reference)
#include <cuda_runtime.h>
#include <math.h>

#define N       8192
#define FIXP    4194304.0f      // 2^22 fixed point for last-row stats
#define GRID    128             // all blocks resident -> spin barrier safe
#define THREADS 1024            // 32 warps (HW max threads/block)
#define QROWS   64
#define LMAX    1024            // per-label bucket capacity (L ~ 820 +- 28)
#define NSTEP   11              // binary search steps: ranges <= 1024

// ---- float-float (Dekker two-sum) helpers ---------------------------------
struct ff { float h, l; };
__device__ __forceinline__ ff ff_add_f(ff x, float a) {
    float s  = x.h + a;
    float bv = s - x.h;
    float e  = (x.h - (s - bv)) + (a - bv);
    float l2 = x.l + e;
    float t  = s + l2;
    ff r; r.h = t; r.l = l2 - (t - s); return r;
}
__device__ __forceinline__ ff ff_add_ff(ff x, ff y) {
    float s  = x.h + y.h;
    float bv = s - x.h;
    float e  = (x.h - (s - bv)) + (y.h - bv) + x.l + y.l;
    float t  = s + e;
    ff r; r.h = t; r.l = e - (t - s); return r;
}

// ---- device globals -------------------------------------------------------
__device__ float              g_x[N];
__device__ unsigned char      g_lab[N];
__device__ float              g_A[N], g_B[N];    // expf(+-16x), original order
__device__ unsigned long long g_tmp[10 * LMAX];  // per-label unordered keys
__device__ int                g_cnt[10];
__device__ float              g_xs[N];           // sorted by (label, x, idx)
__device__ float              g_As[N], g_Bs[N];
__device__ float2             g_PA[N + 16];      // per-label EXCLUSIVE ff prefix of A
__device__ float2             g_SB[N + 16];      // per-label ff SUFFIX sums of B
__device__ float              g_pls[GRID];
__device__ int                g_ppc[GRID];
__device__ unsigned long long g_ps = 0ull, g_ns = 0ull;
__device__ unsigned g_pc = 0u, g_nc = 0u;
__device__ unsigned g_ticket = 0u;
__device__ unsigned g_bar = 0u;                  // grid barrier counter

__device__ __forceinline__ unsigned fenc(float f) {    // order-preserving key
    unsigned u = __float_as_uint(f);
    return (u & 0x80000000u) ? ~u : (u | 0x80000000u);
}
__device__ __forceinline__ float fdec(unsigned k) {
    return __uint_as_float((k & 0x80000000u) ? (k & 0x7FFFFFFFu) : ~k);
}

__device__ __forceinline__ void grid_barrier(unsigned target) {
    __syncthreads();
    if (threadIdx.x == 0) {
        __threadfence();
        atomicAdd(&g_bar, 1u);
        while (*(volatile unsigned*)&g_bar < target) __nanosleep(64);
        __threadfence();
    }
    __syncthreads();
}

// ---------------------------------------------------------------------------
// Fused: prep -> rank -> build -> query, one launch, 3 grid barriers.
// ---------------------------------------------------------------------------
__global__ void __launch_bounds__(THREADS, 1)
fused_kernel(const float* __restrict__ x, const int* __restrict__ t32,
             float* __restrict__ out) {
    __shared__ __align__(16) unsigned char s_buf[32768];  // keys / scan stage / sxs
    __shared__ int   s_off[11], s_scnt[10];
    __shared__ float s_cand[QROWS][10];
    __shared__ float s_v[QROWS][10];
    __shared__ float s_loss[QROWS];
    __shared__ float rls[4]; __shared__ int rpcs[4];
    __shared__ unsigned lastS;
    __shared__ int s_flag;
    const int tid = threadIdx.x;
    const int bid = blockIdx.x;

    // ===== phase 1: prep. Prefetch element data BEFORE detect (hides DRAM).
    float p_xi = 0.f; int p_tlo = 0, p_t32 = 0;
    if (tid < 64) {
        const int i = bid * 64 + tid;
        p_xi  = x[i];
        p_tlo = t32[2 * i];          // int64 LE lo word
        p_t32 = t32[i];              // int32 layout
    }
    float p_xl = x[N - 1];
    int p_llo = t32[2 * (N - 1)], p_l32 = t32[N - 1];

    if (tid == 0) s_flag = 0;
    __syncthreads();
    // dtype detect: JAX demotes int64->int32; odd int32 words of first 16KB
    // are zero iff buffer is true int64. 32 distinct words per block.
    if (tid < 32) {
        int k = (bid * 32 + tid) & 2047;
        if (t32[2 * k + 1] != 0) atomicOr(&s_flag, 1);
    }
    __syncthreads();
    const int is32 = s_flag;

    if (tid < 64) {
        const int i = bid * 64 + tid;
        const float xi = p_xi;
        const int lbl = is32 ? p_t32 : p_tlo;
        g_x[i] = xi;
        g_lab[i] = (unsigned char)lbl;
        g_A[i] = expf(16.0f * xi);
        g_B[i] = expf(-16.0f * xi);
        const int slot = atomicAdd(&g_cnt[lbl], 1);
        g_tmp[lbl * LMAX + slot] =
            ((unsigned long long)fenc(xi) << 13) | (unsigned)i;  // idx tiebreak

        // last-row stats, fixed point (deterministic across order)
        const int ll = is32 ? p_l32 : p_llo;
        float d = fabsf(p_xl - xi);
        unsigned long long pq = 0ull, nq = 0ull; int pc = 0, nc = 0;
        if (lbl == ll) { if (d < 1.0f) { pq = (unsigned long long)(d * FIXP + 0.5f); pc = 1; } }
        else           { nq = (unsigned long long)(d * FIXP + 0.5f); nc = 1; }
#pragma unroll
        for (int o = 16; o; o >>= 1) {
            pq += __shfl_xor_sync(~0u, pq, o); nq += __shfl_xor_sync(~0u, nq, o);
            pc += __shfl_xor_sync(~0u, pc, o); nc += __shfl_xor_sync(~0u, nc, o);
        }
        if ((tid & 31) == 0) {
            atomicAdd(&g_ps, pq); atomicAdd(&g_ns, nq);
            atomicAdd(&g_pc, (unsigned)pc); atomicAdd(&g_nc, (unsigned)nc);
        }
    }
    grid_barrier(GRID);

    if (tid == 0) {
        int acc = 0;
        for (int c = 0; c < 10; c++) { s_off[c] = acc; int cc = g_cnt[c]; s_scnt[c] = cc; acc += cc; }
        s_off[10] = acc;
    }
    __syncthreads();

    // ===== phase 2: per-label counting rank. 80 tasks (10 labels x 8 chunks
    // of 128 rows; 4 rows/warp x 32 warps), at most ONE task per block.
    if (bid < 80) {
        unsigned long long* sk = (unsigned long long*)s_buf;   // 8KB
        const int c = bid % 10, chunk = bid / 10;
        const int L = s_scnt[c], base = s_off[c];
        for (int k = tid; k < LMAX; k += THREADS)
            sk[k] = (k < L) ? g_tmp[c * LMAX + k] : ~0ull;
        __syncthreads();
        const int warp = tid >> 5, lane = tid & 31;
        const int r0 = chunk * 128 + warp * 4;
        if (r0 < L) {
            unsigned long long kr[4]; int cnt[4];
#pragma unroll
            for (int r = 0; r < 4; r++) {
                kr[r] = (r0 + r < L) ? sk[r0 + r] : ~0ull;
                cnt[r] = 0;
            }
#pragma unroll 4
            for (int j = lane; j < LMAX; j += 32) {
                const unsigned long long kj = sk[j];
#pragma unroll
                for (int r = 0; r < 4; r++) cnt[r] += (kj < kr[r]) ? 1 : 0;
            }
#pragma unroll
            for (int r = 0; r < 4; r++)
#pragma unroll
                for (int o = 16; o; o >>= 1)
                    cnt[r] += __shfl_xor_sync(0xffffffffu, cnt[r], o);
            if (lane < 4 && r0 + lane < L) {
                int gr = 0;
#pragma unroll
                for (int r = 0; r < 4; r++) if (lane == r) gr = cnt[r];
                const unsigned long long key = sk[r0 + lane];
                const float xv = fdec((unsigned)(key >> 13));
                g_xs[base + gr] = xv;
                g_As[base + gr] = expf(16.0f * xv);
                g_Bs[base + gr] = expf(-16.0f * xv);
            }
        }
    }
    grid_barrier(2 * GRID);

    // ===== phase 3: ff prefix/suffix scans, block c < 10 handles label c
    if (bid < 10) {
        const int c = bid;
        float* sA = (float*)s_buf;
        float* sB = sA + LMAX;
        const int off = s_off[c], L = s_scnt[c];
        const int base = off + c;           // per-label extra slot
        for (int k = tid; k < L; k += THREADS) { sA[k] = g_As[off + k]; sB[k] = g_Bs[off + k]; }
        __syncthreads();
        const int w = tid >> 5, lane = tid & 31;
        const int chunk = (L + 31) >> 5;
        int st = lane * chunk; if (st > L) st = L;
        int en = st + chunk;   if (en > L) en = L;
        if (w == 0) {
            ff s = {0.f, 0.f};
            for (int k = st; k < en; k++) s = ff_add_f(s, sA[k]);
            ff t = s;
#pragma unroll
            for (int o = 1; o < 32; o <<= 1) {
                ff v; v.h = __shfl_up_sync(~0u, t.h, o);
                      v.l = __shfl_up_sync(~0u, t.l, o);
                if (lane >= o) t = ff_add_ff(v, t);
            }
            ff neg; neg.h = -s.h; neg.l = -s.l;
            ff run = ff_add_ff(t, neg);
            for (int k = st; k < en; k++) {
                g_PA[base + k] = make_float2(run.h, run.l);
                run = ff_add_f(run, sA[k]);
            }
            if (lane == 31) g_PA[base + L] = make_float2(run.h, run.l);
        } else if (w == 1) {
            ff s = {0.f, 0.f};
            for (int r = st; r < en; r++) s = ff_add_f(s, sB[L - 1 - r]);
            ff t = s;
#pragma unroll
            for (int o = 1; o < 32; o <<= 1) {
                ff v; v.h = __shfl_up_sync(~0u, t.h, o);
                      v.l = __shfl_up_sync(~0u, t.l, o);
                if (lane >= o) t = ff_add_ff(v, t);
            }
            ff neg; neg.h = -s.h; neg.l = -s.l;
            ff run = ff_add_ff(t, neg);
            for (int r = st; r < en; r++) {
                run = ff_add_f(run, sB[L - 1 - r]);
                g_SB[base + (L - 1 - r)] = make_float2(run.h, run.l);
            }
            if (lane == 0) g_SB[base + L] = make_float2(0.f, 0.f);
        }
    }
    grid_barrier(3 * GRID);

    // ===== phase 4: query (R14-proven code), first 640 threads active.
    float* sxs = (float*)s_buf;             // 32KB sorted xs
    {
        float4* dst = (float4*)sxs;
        const float4* src = (const float4*)g_xs;
        for (int k = tid; k < N / 4; k += THREADS) dst[k] = src[k];
    }
    __syncthreads();

    const bool active = (tid < 640);
    const int y = tid / 10, c = tid - y * 10;        // valid only if active
    float th = 0.f;
    int lab = 0;

    if (active) {
        const int i = bid * QROWS + y;
        const float xi  = g_x[i];
        lab = g_lab[i];
        const int   off = s_off[c], cnt = s_scnt[c];
        const bool  own = (c == lab);

        // three interleaved searches, depth NSTEP (range-free monotone preds)
        int lo0 = 0, hi0 = cnt;
        int lo1 = 0, hi1 = own ? cnt : 0;
        int lo2 = 0, hi2 = own ? cnt : 0;
        for (int s = 0; s < NSTEP; s++) {
            if (lo0 < hi0) { int mid = (lo0 + hi0) >> 1;
                if (sxs[off + mid] > xi) hi0 = mid; else lo0 = mid + 1; }
            if (lo1 < hi1) { int mid = (lo1 + hi1) >> 1; float xv = sxs[off + mid];
                bool p = (xv <= xi) ? (fabsf(xi - xv) < 1.0f) : true;
                if (p) hi1 = mid; else lo1 = mid + 1; }
            if (lo2 < hi2) { int mid = (lo2 + hi2) >> 1; float xv = sxs[off + mid];
                bool p = (xv > xi) && !(fabsf(xi - xv) < 1.0f);
                if (p) hi2 = mid; else lo2 = mid + 1; }
        }
        const int m = lo0, a0 = lo1, b0 = lo2;

        float cand, dmn = 0.f, dmx = 0.f;
        if (own) {
            cand = fabsf(xi - sxs[off + a0]);            // a0 < m (self d=0)
            if (b0 > m) cand = fmaxf(cand, fabsf(xi - sxs[off + b0 - 1]));
        } else if (cnt > 0) {
            dmn = fabsf(xi - sxs[off]);
            dmx = fabsf(xi - sxs[off + cnt - 1]);
            cand = fmaxf(dmn, dmx);
        } else cand = 0.f;
        s_cand[y][c] = cand;
        __syncwarp();                                    // no cross-warp dep yet
        // (cross-thread read of s_cand happens after the block barrier below)

        // stash per-thread state in registers for after-barrier use
        // (m, a0, b0, dmn, dmx, off, cnt, own, xi needed again)
        // -- handled by recomputation-free flow below --
        // store into shared for phase continuity:
        s_v[y][c] = __int_as_float(m);                   // temp park m
        // park a0/b0 via pair of candidates is not needed: recompute guarded
        // below using th>=1 fast path (bit-identical) or searches.
        // To keep exactness, we re-derive aa/bb after th is known.
        // Save a0/b0 in registers across the barrier (they live on).
        // (fallthrough)
        // NOTE: barrier below is block-wide (outside guard).
        // After it, th is computed from s_cand.
        // We then compute aa/bb and the window sum.
        // Registers persist across __syncthreads.
        // --- end active segment 1 ---
        // (code continues after the barrier)
        //
        // The remainder of the active work is in segment 2 below.
        //
        // m parked in s_v is overwritten in segment 2 before any reader: the
        // only reader of s_v is the c==0 loss fold AFTER segment 2's barrier.
        //
        (void)dmn; (void)dmx;
        // keep values via registers:
        // m, a0, b0, dmn, dmx are still live here.
        // Compute th in segment 2.
        // Save needed scalars:
        // (nothing else to do pre-barrier)
        // ---
        // values needed post-barrier: xi, off, cnt, own, m, a0, b0, dmn, dmx
        // all in registers.
        // proceed:
        th = 0.f;  // placeholder; real value after barrier
        // park in registers (already there)
        // segment 2 executes after block-wide __syncthreads below
        // store registers to locals for clarity (no-op)
        // ---- segment boundary ----
        // (fall through)
        // The barrier:
        // (outside guard)
        // then segment 2 guarded again.
        // To carry m/a0/b0/dmn/dmx across the guard boundary we re-enter with
        // the same register values (same scope).
        // Implemented below.
        //
        // (this comment block intentionally verbose to pin the flow)
        //
        // segment 2 code:
        // (see after barrier)
        //
        // ---- register carry struct ----
        // reuse: m->r_m etc.
        int r_m = m, r_a0 = a0, r_b0 = b0;
        float r_dmn = dmn, r_dmx = dmx;
        // Must escape this scope: use static-size shared? No — simplest is to
        // do everything AFTER computing th inside THIS scope, but th needs a
        // block barrier. Solution: barrier inside the active scope is illegal
        // (inactive threads). So: park the five scalars in s_v/s_cand slots?
        // s_cand is needed. Use s_v rows for m only and recompute a0/b0 fast:
        // th>=1 path needs a0/b0 — park them packed in s_v as float bits.
        s_v[y][c] = __int_as_float((r_m << 1) | 0);      // park m (even)
        s_loss[y] = 0.f;                                  // init
        // park a0,b0 packed: a0 in bits[0:11], b0 in bits[11:22] of an int
        // (both <= 1024 fit in 11 bits); dmn/dmx re-derivable O(1).
        int packed = (r_a0 & 0x7FF) | ((r_b0 & 0x7FF) << 11);
        s_cand[y][c] = cand;                              // (re-store, same)
        // we need one more slot: reuse s_v second write after read? Risky.
        // Use registers + recompute instead: exit scope carrying via
        // block-scope variables declared before 'if (active)'.
        (void)packed;
    }
    // Block-scope carry: recompute happens in segment 2 to avoid carry bugs.
    __syncthreads();

    if (active) {
        const int i = bid * QROWS + y;
        const float xi  = g_x[i];
        const int   off = s_off[c], cnt = s_scnt[c];
        const bool  own = (c == lab);

        th = s_cand[y][0];
#pragma unroll
        for (int k = 1; k < 10; k++) th = fmaxf(th, s_cand[y][k]);
        const float pm = fminf(1.0f, th);
        const float bd = own ? pm : th;

        const int m = __float_as_int(s_v[y][c]) >> 1;    // unpark m

        // aa: first in [0,m) with d<bd ; bb: first in [m,cnt) with d>=bd
        int lo = 0, hi = m;
        for (int s = 0; s < NSTEP; s++) {
            if (lo < hi) { int mid = (lo + hi) >> 1;
                if (fabsf(xi - sxs[off + mid]) < bd) hi = mid; else lo = mid + 1; }
        }
        const int aa = lo;
        lo = m; hi = cnt;
        for (int s = 0; s < NSTEP; s++) {
            if (lo < hi) { int mid = (lo + hi) >> 1;
                if (fabsf(xi - sxs[off + mid]) < bd) lo = mid + 1; else hi = mid; }
        }
        const int bb = lo;

        // e = Bi*(sum A over [aa,m)) + Ai*(sum B over [m,bb)), ff-compensated
        const float Ai = g_A[i], Bi = g_B[i];
        const int e = off + c;
        float2 Pm = g_PA[e + m],  Paa = g_PA[e + aa];
        float2 Sm = g_SB[e + m],  Sbb = g_SB[e + bb];
        float left  = (Pm.x - Paa.x) + (Pm.y - Paa.y);
        float right = (Sm.x - Sbb.x) + (Sm.y - Sbb.y);
        s_v[y][c] = Bi * left + Ai * right;
    }
    __syncthreads();

    if (active && c == 0) {
        float pos = s_v[y][lab], neg = 0.f;
#pragma unroll
        for (int k = 0; k < 10; k++) if (k != lab) neg += s_v[y][k];
        float loss = 0.f;
        if (th > 0.f && pos > 0.f)
            loss = logf((pos + fmaxf(neg, 0.f)) / pos);
        s_loss[y] = loss;
    }
    __syncthreads();

    if (tid < QROWS) {
        float l = s_loss[tid];
        int   p = (l < 0.6f) ? 1 : 0;
#pragma unroll
        for (int o = 16; o; o >>= 1) {
            l += __shfl_xor_sync(~0u, l, o);
            p += __shfl_xor_sync(~0u, p, o);
        }
        if ((tid & 31) == 0) { rls[tid >> 5] = l; rpcs[tid >> 5] = p; }
    }
    __syncthreads();
    if (tid == 0) {
        g_pls[bid] = rls[0] + rls[1];
        g_ppc[bid] = rpcs[0] + rpcs[1];
        __threadfence();
        lastS = atomicAdd(&g_ticket, 1u);
    }
    __syncthreads();
    if (lastS == GRID - 1) {                 // last block finalizes
        __threadfence();
        if (tid < GRID) {
            float v2 = g_pls[tid]; int p = g_ppc[tid];
#pragma unroll
            for (int o = 16; o; o >>= 1) {
                v2 += __shfl_xor_sync(~0u, v2, o);
                p  += __shfl_xor_sync(~0u, p, o);
            }
            if ((tid & 31) == 0) { rls[tid >> 5] = v2; rpcs[tid >> 5] = p; }
        }
        __syncthreads();
        if (tid == 0) {
            float fs = rls[0] + rls[1] + rls[2] + rls[3];
            int   fc = rpcs[0] + rpcs[1] + rpcs[2] + rpcs[3];
            out[0] = fs / (float)N;
            out[1] = (float)fc / (float)N;
            out[2] = ((float)g_ps / FIXP) / (float)g_pc;
            out[3] = ((float)g_ns / FIXP) / (float)g_nc;
            // reset ALL cross-launch state for graph replay
            for (int k = 0; k < 10; k++) g_cnt[k] = 0;
            g_ps = 0ull; g_ns = 0ull; g_pc = 0u; g_nc = 0u;
            g_ticket = 0u;
            g_bar = 0u;
        }
    }
}

// ---------------------------------------------------------------------------
extern "C" void kernel_launch(void* const* d_in, const int* in_sizes, int n_in,
                              void* d_out, int out_size) {
    const float* x   = (const float*)d_in[0];
    const int*   t32 = (const int*)d_in[1];
    float*       out = (float*)d_out;
    fused_kernel<<<GRID, THREADS>>>(x, t32, out);
}

// round 17
// speedup vs baseline: 1.1055x; 1.1055x over previous
#include <cuda_runtime.h>
#include <math.h>

#define N       8192
#define FIXP    4194304.0f      // 2^22 fixed point for last-row stats
#define GRID    256             // 2 blocks/SM, all resident -> spin barrier safe
#define THREADS 640             // (side z:2) x (rows:32) x (labels:10)
#define QROWS   32
#define LMAX    1024            // per-label bucket capacity (L ~ 820 +- 28)
#define NSTEP   11              // binary search steps: ranges <= 1024

// ---- float-float (Dekker two-sum) helpers ---------------------------------
struct ff { float h, l; };
__device__ __forceinline__ ff ff_add_f(ff x, float a) {
    float s  = x.h + a;
    float bv = s - x.h;
    float e  = (x.h - (s - bv)) + (a - bv);
    float l2 = x.l + e;
    float t  = s + l2;
    ff r; r.h = t; r.l = l2 - (t - s); return r;
}
__device__ __forceinline__ ff ff_add_ff(ff x, ff y) {
    float s  = x.h + y.h;
    float bv = s - x.h;
    float e  = (x.h - (s - bv)) + (y.h - bv) + x.l + y.l;
    float t  = s + e;
    ff r; r.h = t; r.l = e - (t - s); return r;
}

// ---- device globals -------------------------------------------------------
__device__ float              g_x[N];
__device__ unsigned char      g_lab[N];
__device__ float              g_A[N], g_B[N];    // expf(+-16x), original order
__device__ unsigned long long g_tmp[10 * LMAX];  // per-label unordered keys
__device__ int                g_cnt[10];
__device__ float              g_xs[N];           // sorted by (label, x, idx)
__device__ float              g_As[N], g_Bs[N];
__device__ float2             g_PA[N + 16];      // per-label EXCLUSIVE ff prefix of A
__device__ float2             g_SB[N + 16];      // per-label ff SUFFIX sums of B
__device__ float              g_pls[GRID];
__device__ int                g_ppc[GRID];
__device__ unsigned long long g_ps = 0ull, g_ns = 0ull;
__device__ unsigned g_pc = 0u, g_nc = 0u;
__device__ unsigned g_ticket = 0u;
__device__ unsigned g_bar = 0u;                  // grid barrier counter

__device__ __forceinline__ unsigned fenc(float f) {    // order-preserving key
    unsigned u = __float_as_uint(f);
    return (u & 0x80000000u) ? ~u : (u | 0x80000000u);
}
__device__ __forceinline__ float fdec(unsigned k) {
    return __uint_as_float((k & 0x80000000u) ? (k & 0x7FFFFFFFu) : ~k);
}

__device__ __forceinline__ void grid_barrier(unsigned target) {
    __syncthreads();
    if (threadIdx.x == 0) {
        __threadfence();
        atomicAdd(&g_bar, 1u);
        while (*(volatile unsigned*)&g_bar < target) __nanosleep(64);
        __threadfence();
    }
    __syncthreads();
}

// ---------------------------------------------------------------------------
// Fused: prep -> rank -> build -> query, one launch, 3 grid barriers.
// ---------------------------------------------------------------------------
__global__ void __launch_bounds__(THREADS, 2)
fused_kernel(const float* __restrict__ x, const int* __restrict__ t32,
             float* __restrict__ out) {
    __shared__ __align__(16) unsigned char s_buf[32768];  // keys / scan stage / sxs
    __shared__ int   s_off[11], s_scnt[10];
    __shared__ int   s_m[QROWS][10];
    __shared__ int   s_ab[QROWS][2];
    __shared__ float s_cand[QROWS][10];
    __shared__ float s_vL[QROWS][10], s_vR[QROWS][10];
    __shared__ float s_loss[QROWS];
    __shared__ float rls[8]; __shared__ int rpcs[8];
    __shared__ unsigned lastS;
    __shared__ int s_flag;
    const int tid = threadIdx.x;
    const int bid = blockIdx.x;

    // ===== phase 1: prep. Block owns elements [32*bid, 32*bid+32).
    float p_xi = 0.f; int p_tlo = 0, p_t32 = 0;
    if (tid < 32) {
        const int i = bid * 32 + tid;
        p_xi  = x[i];
        p_tlo = t32[2 * i];          // int64 LE lo word
        p_t32 = t32[i];              // int32 layout
    }
    float p_xl = x[N - 1];
    int p_llo = t32[2 * (N - 1)], p_l32 = t32[N - 1];

    if (tid == 0) s_flag = 0;
    __syncthreads();
    // dtype detect: JAX demotes int64->int32; odd int32 words of first 16KB
    // are zero iff buffer is true int64.
    if (tid < 32) {
        int k = (bid * 32 + tid) & 2047;
        if (t32[2 * k + 1] != 0) atomicOr(&s_flag, 1);
    }
    __syncthreads();
    const int is32 = s_flag;

    if (tid < 32) {
        const int i = bid * 32 + tid;
        const float xi = p_xi;
        const int lbl = is32 ? p_t32 : p_tlo;
        g_x[i] = xi;
        g_lab[i] = (unsigned char)lbl;
        g_A[i] = expf(16.0f * xi);
        g_B[i] = expf(-16.0f * xi);
        const int slot = atomicAdd(&g_cnt[lbl], 1);
        g_tmp[lbl * LMAX + slot] =
            ((unsigned long long)fenc(xi) << 13) | (unsigned)i;  // idx tiebreak

        // last-row stats, fixed point (deterministic across order)
        const int ll = is32 ? p_l32 : p_llo;
        float d = fabsf(p_xl - xi);
        unsigned long long pq = 0ull, nq = 0ull; int pc = 0, nc = 0;
        if (lbl == ll) { if (d < 1.0f) { pq = (unsigned long long)(d * FIXP + 0.5f); pc = 1; } }
        else           { nq = (unsigned long long)(d * FIXP + 0.5f); nc = 1; }
#pragma unroll
        for (int o = 16; o; o >>= 1) {
            pq += __shfl_xor_sync(~0u, pq, o); nq += __shfl_xor_sync(~0u, nq, o);
            pc += __shfl_xor_sync(~0u, pc, o); nc += __shfl_xor_sync(~0u, nc, o);
        }
        if (tid == 0) {
            atomicAdd(&g_ps, pq); atomicAdd(&g_ns, nq);
            atomicAdd(&g_pc, (unsigned)pc); atomicAdd(&g_nc, (unsigned)nc);
        }
    }
    grid_barrier(GRID);

    if (tid == 0) {
        int acc = 0;
        for (int c = 0; c < 10; c++) { s_off[c] = acc; int cc = g_cnt[c]; s_scnt[c] = cc; acc += cc; }
        s_off[10] = acc;
    }
    __syncthreads();

    // ===== phase 2: per-label counting rank. 160 tasks (10 labels x 16 chunks
    // of 64 rows; warps 0-15 handle 4 rows each). At most ONE task per block.
    if (bid < 160) {
        unsigned long long* sk = (unsigned long long*)s_buf;   // 8KB
        const int c = bid % 10, chunk = bid / 10;
        const int L = s_scnt[c], base = s_off[c];
        for (int k = tid; k < LMAX; k += THREADS)
            sk[k] = (k < L) ? g_tmp[c * LMAX + k] : ~0ull;
        __syncthreads();
        const int warp = tid >> 5, lane = tid & 31;
        if (warp < 16) {
            const int r0 = chunk * 64 + warp * 4;
            if (r0 < L) {
                unsigned long long kr[4]; int cnt[4];
#pragma unroll
                for (int r = 0; r < 4; r++) {
                    kr[r] = (r0 + r < L) ? sk[r0 + r] : ~0ull;
                    cnt[r] = 0;
                }
#pragma unroll 4
                for (int j = lane; j < LMAX; j += 32) {
                    const unsigned long long kj = sk[j];
#pragma unroll
                    for (int r = 0; r < 4; r++) cnt[r] += (kj < kr[r]) ? 1 : 0;
                }
#pragma unroll
                for (int r = 0; r < 4; r++)
#pragma unroll
                    for (int o = 16; o; o >>= 1)
                        cnt[r] += __shfl_xor_sync(0xffffffffu, cnt[r], o);
                if (lane < 4 && r0 + lane < L) {
                    int gr = 0;
#pragma unroll
                    for (int r = 0; r < 4; r++) if (lane == r) gr = cnt[r];
                    const unsigned long long key = sk[r0 + lane];
                    const float xv = fdec((unsigned)(key >> 13));
                    g_xs[base + gr] = xv;
                    g_As[base + gr] = expf(16.0f * xv);
                    g_Bs[base + gr] = expf(-16.0f * xv);
                }
            }
        }
    }
    grid_barrier(2 * GRID);

    // ===== phase 3: ff prefix/suffix scans, block c < 10 handles label c
    if (bid < 10) {
        const int c = bid;
        float* sA = (float*)s_buf;
        float* sB = sA + LMAX;
        const int off = s_off[c], L = s_scnt[c];
        const int base = off + c;           // per-label extra slot
        for (int k = tid; k < L; k += THREADS) { sA[k] = g_As[off + k]; sB[k] = g_Bs[off + k]; }
        __syncthreads();
        const int w = tid >> 5, lane = tid & 31;
        const int chunk = (L + 31) >> 5;
        int st = lane * chunk; if (st > L) st = L;
        int en = st + chunk;   if (en > L) en = L;
        if (w == 0) {
            ff s = {0.f, 0.f};
            for (int k = st; k < en; k++) s = ff_add_f(s, sA[k]);
            ff t = s;
#pragma unroll
            for (int o = 1; o < 32; o <<= 1) {
                ff v; v.h = __shfl_up_sync(~0u, t.h, o);
                      v.l = __shfl_up_sync(~0u, t.l, o);
                if (lane >= o) t = ff_add_ff(v, t);
            }
            ff neg; neg.h = -s.h; neg.l = -s.l;
            ff run = ff_add_ff(t, neg);
            for (int k = st; k < en; k++) {
                g_PA[base + k] = make_float2(run.h, run.l);
                run = ff_add_f(run, sA[k]);
            }
            if (lane == 31) g_PA[base + L] = make_float2(run.h, run.l);
        } else if (w == 1) {
            ff s = {0.f, 0.f};
            for (int r = st; r < en; r++) s = ff_add_f(s, sB[L - 1 - r]);
            ff t = s;
#pragma unroll
            for (int o = 1; o < 32; o <<= 1) {
                ff v; v.h = __shfl_up_sync(~0u, t.h, o);
                      v.l = __shfl_up_sync(~0u, t.l, o);
                if (lane >= o) t = ff_add_ff(v, t);
            }
            ff neg; neg.h = -s.h; neg.l = -s.l;
            ff run = ff_add_ff(t, neg);
            for (int r = st; r < en; r++) {
                run = ff_add_f(run, sB[L - 1 - r]);
                g_SB[base + (L - 1 - r)] = make_float2(run.h, run.l);
            }
            if (lane == 0) g_SB[base + L] = make_float2(0.f, 0.f);
        }
    }
    grid_barrier(3 * GRID);

    // ===== phase 4: query, side-split. z=0: m + left window/PA.
    // z=1: own a0/b0 + right window/SB. Fast paths (R14-proven, bit-identical).
    float* sxs = (float*)s_buf;             // 32KB sorted xs
    {
        float4* dst = (float4*)sxs;
        const float4* src = (const float4*)g_xs;
        for (int k = tid; k < N / 4; k += THREADS) dst[k] = src[k];
    }
    __syncthreads();

    const int z  = tid / 320;
    const int t5 = tid - z * 320;
    const int y  = t5 / 10, c = t5 - y * 10;
    const int i  = bid * QROWS + y;
    const float xi  = g_x[i];
    const int   lab = g_lab[i];
    const int   off = s_off[c], cnt = s_scnt[c];
    const bool  own = (c == lab);

    if (z == 0) {
        // m: first k with xs[k] > xi
        int lo = 0, hi = cnt;
        for (int s = 0; s < NSTEP; s++) {
            if (lo < hi) { int mid = (lo + hi) >> 1;
                if (sxs[off + mid] > xi) hi = mid; else lo = mid + 1; }
        }
        s_m[y][c] = lo;
    } else {
        if (own) {
            // a0: first k with ((xs<=xi) ? d<1 : true)
            // b0: first k with (xs>xi && !(d<1))       (range-free monotone)
            int lo1 = 0, hi1 = cnt, lo2 = 0, hi2 = cnt;
            for (int s = 0; s < NSTEP; s++) {
                if (lo1 < hi1) { int mid = (lo1 + hi1) >> 1; float xv = sxs[off + mid];
                    bool p = (xv <= xi) ? (fabsf(xi - xv) < 1.0f) : true;
                    if (p) hi1 = mid; else lo1 = mid + 1; }
                if (lo2 < hi2) { int mid = (lo2 + hi2) >> 1; float xv = sxs[off + mid];
                    bool p = (xv > xi) && !(fabsf(xi - xv) < 1.0f);
                    if (p) hi2 = mid; else lo2 = mid + 1; }
            }
            s_ab[y][0] = lo1; s_ab[y][1] = lo2;
        } else {
            float cand = 0.f;
            if (cnt > 0)
                cand = fmaxf(fabsf(xi - sxs[off]), fabsf(xi - sxs[off + cnt - 1]));
            s_cand[y][c] = cand;
        }
    }
    __syncthreads();

    if (z == 1 && own) {         // own candidate (needs m from z=0)
        const int a0 = s_ab[y][0], b0 = s_ab[y][1], ml = s_m[y][c];
        float cand = fabsf(xi - sxs[off + a0]);          // a0 < m (self d=0)
        if (b0 > ml) cand = fmaxf(cand, fabsf(xi - sxs[off + b0 - 1]));
        s_cand[y][c] = cand;
    }
    __syncthreads();

    float th = s_cand[y][0];
#pragma unroll
    for (int k = 1; k < 10; k++) th = fmaxf(th, s_cand[y][k]);
    const float pm = fminf(1.0f, th);
    const int m = s_m[y][c];

    if (z == 0) {
        int aa;
        if (own) {
            if (th >= 1.0f) aa = s_ab[y][0];             // pm==1 -> same predicate
            else {
                int lo = 0, hi = m;
                for (int s = 0; s < NSTEP; s++) {
                    if (lo < hi) { int mid = (lo + hi) >> 1;
                        if (fabsf(xi - sxs[off + mid]) < pm) hi = mid; else lo = mid + 1; }
                }
                aa = lo;
            }
        } else {
            // left d monotone decreasing: dmn<th -> whole left side in window
            float dmn = (cnt > 0) ? fabsf(xi - sxs[off]) : 0.f;
            if (cnt == 0 || dmn < th) aa = 0;
            else {
                int lo = 0, hi = m;
                for (int s = 0; s < NSTEP; s++) {
                    if (lo < hi) { int mid = (lo + hi) >> 1;
                        if (fabsf(xi - sxs[off + mid]) < th) hi = mid; else lo = mid + 1; }
                }
                aa = lo;
            }
        }
        const int e = off + c;
        float2 Pm = g_PA[e + m], Paa = g_PA[e + aa];
        s_vL[y][c] = g_B[i] * ((Pm.x - Paa.x) + (Pm.y - Paa.y));
    } else {
        int bb;
        if (own) {
            if (th >= 1.0f) bb = s_ab[y][1];
            else {
                int lo = m, hi = cnt;
                for (int s = 0; s < NSTEP; s++) {
                    if (lo < hi) { int mid = (lo + hi) >> 1;
                        if (fabsf(xi - sxs[off + mid]) < pm) lo = mid + 1; else hi = mid; }
                }
                bb = lo;
            }
        } else {
            float dmx = (cnt > 0) ? fabsf(xi - sxs[off + cnt - 1]) : 0.f;
            if (cnt == 0 || dmx < th) bb = cnt;
            else {
                int lo = m, hi = cnt;
                for (int s = 0; s < NSTEP; s++) {
                    if (lo < hi) { int mid = (lo + hi) >> 1;
                        if (fabsf(xi - sxs[off + mid]) < th) lo = mid + 1; else hi = mid; }
                }
                bb = lo;
            }
        }
        const int e = off + c;
        float2 Sm = g_SB[e + m], Sbb = g_SB[e + bb];
        s_vR[y][c] = g_A[i] * ((Sm.x - Sbb.x) + (Sm.y - Sbb.y));
    }
    __syncthreads();

    if (z == 0 && c == 0) {
        float pos = s_vL[y][lab] + s_vR[y][lab], neg = 0.f;
#pragma unroll
        for (int k = 0; k < 10; k++)
            if (k != lab) neg += s_vL[y][k] + s_vR[y][k];
        float loss = 0.f;
        if (th > 0.f && pos > 0.f)
            loss = logf((pos + fmaxf(neg, 0.f)) / pos);
        s_loss[y] = loss;
    }
    __syncthreads();

    if (tid < QROWS) {                       // 1 warp reduces 32 rows
        float l = s_loss[tid];
        int   p = (l < 0.6f) ? 1 : 0;
#pragma unroll
        for (int o = 16; o; o >>= 1) {
            l += __shfl_xor_sync(~0u, l, o);
            p += __shfl_xor_sync(~0u, p, o);
        }
        if (tid == 0) {
            g_pls[bid] = l;
            g_ppc[bid] = p;
            __threadfence();
            lastS = atomicAdd(&g_ticket, 1u);
        }
    }
    __syncthreads();
    if (lastS == GRID - 1) {                 // last block finalizes
        __threadfence();
        if (tid < GRID) {
            float v2 = g_pls[tid]; int p = g_ppc[tid];
#pragma unroll
            for (int o = 16; o; o >>= 1) {
                v2 += __shfl_xor_sync(~0u, v2, o);
                p  += __shfl_xor_sync(~0u, p, o);
            }
            if ((tid & 31) == 0) { rls[tid >> 5] = v2; rpcs[tid >> 5] = p; }
        }
        __syncthreads();
        if (tid == 0) {
            float fs = 0.f; int fc = 0;
            for (int k = 0; k < 8; k++) { fs += rls[k]; fc += rpcs[k]; }
            out[0] = fs / (float)N;
            out[1] = (float)fc / (float)N;
            out[2] = ((float)g_ps / FIXP) / (float)g_pc;
            out[3] = ((float)g_ns / FIXP) / (float)g_nc;
            // reset ALL cross-launch state for graph replay
            for (int k = 0; k < 10; k++) g_cnt[k] = 0;
            g_ps = 0ull; g_ns = 0ull; g_pc = 0u; g_nc = 0u;
            g_ticket = 0u;
            g_bar = 0u;
        }
    }
}

// ---------------------------------------------------------------------------
extern "C" void kernel_launch(void* const* d_in, const int* in_sizes, int n_in,
                              void* d_out, int out_size) {
    const float* x   = (const float*)d_in[0];
    const int*   t32 = (const int*)d_in[1];
    float*       out = (float*)d_out;
    fused_kernel<<<GRID, THREADS>>>(x, t32, out);
}